// round 11
// baseline (speedup 1.0000x reference)
#include <cuda_runtime.h>
#include <cstdint>

// Fused batched GCN, one CTA per graph (512 x 100 nodes, deg 16), fp32.
// 512 threads / 16 warps; warp owns rows {warp + 16*i, i<7}.
// Crossbar-lean design: aggregated features (A) and h1 live in REGISTERS,
// distributed per-lane by k-chunk; GEMM k-broadcasts use __shfl_sync (lane
// network, not the smem crossbar). SMEM holds only feat, W1, W2, edges and
// small head scratch (t/t2/head overlay the dead feat buffer).
// GEMMs use packed fma.rn.f32x2. Heads: softmax over length-1 token == 1
// -> Z=(x@Wv^T)@Wo^T; Wq/Wk dead.

#define NPG   100
#define DEG   16
#define DIN   100
#define H1D   100
#define DG    20
#define P2D   200
#define P3D   100

#define PA    106   // pitch of W1/W2 tiles (odd u64-stride -> conflict-free)
#define PT    21    // pitch of 20-wide buffers

// ---- shared memory layout (float element offsets) ----
#define OFF_X     0                      // 10000  feat (pitch 100); later overlay
#define OFF_W1    (OFF_X  + 10000)       // 10600  W1 (100 x pitch106)
#define OFF_W2    (OFF_W1 + 10600)       // 2120   W2 (20 x pitch106)
#define OFF_E     (OFF_W2 + 2120)        // 1600 ints
#define OFF_SF    (OFF_E  + 1600)        // 200
#define OFF_X3    (OFF_SF + 200)         // 100
#define SMEM_ELEMS (OFF_X3 + 112)
#define SMEM_BYTES (SMEM_ELEMS * 4)      // ~98 KB

// overlay inside the feat region (valid after the post-GEMM1 barrier)
#define OVL_T     (OFF_X + 0)            // 100*21 = 2100
#define OVL_T2    (OFF_X + 2112)         // 2100
#define OVL_PART  (OFF_X + 4224)         // 16*20 = 320
#define OVL_VP2   (OFF_X + 4544)         // 512
#define OVL_VP3   (OFF_X + 5056)         // 512
#define OVL_VV    (OFF_X + 5568)         // 64
#define OVL_HG2   (OFF_X + 5632)         // 20
#define OVL_O10   (OFF_X + 5652)         // 12

typedef unsigned long long u64;

static __device__ __forceinline__ void ffma2(u64& d, u64 a, u64 b) {
    asm("fma.rn.f32x2 %0, %1, %2, %0;" : "+l"(d) : "l"(a), "l"(b));
}
static __device__ __forceinline__ void fadd2(u64& d, u64 a) {
    asm("add.rn.f32x2 %0, %0, %1;" : "+l"(d) : "l"(a));
}
static __device__ __forceinline__ void fmul2(u64& d, u64 a) {
    asm("mul.rn.f32x2 %0, %0, %1;" : "+l"(d) : "l"(a));
}
static __device__ __forceinline__ float hsum2(u64 v) {
    float lo = __uint_as_float((unsigned)(v & 0xffffffffu));
    float hi = __uint_as_float((unsigned)(v >> 32));
    return lo + hi;
}
static __device__ __forceinline__ u64 shfl64(u64 v, int src) {
    return __shfl_sync(0xffffffffu, v, src);
}
static __device__ __forceinline__ u64 pack2(float lo, float hi) {
    return (u64)__float_as_uint(lo) | ((u64)__float_as_uint(hi) << 32);
}

__global__ __launch_bounds__(512, 1)
void net_kernel(const float* __restrict__ feat,
                const int*   __restrict__ edge_src,
                const float* __restrict__ self_feat,
                const float* __restrict__ x3d,
                const float* __restrict__ W1,  const float* __restrict__ b1,
                const float* __restrict__ W2,  const float* __restrict__ b2,
                const float* __restrict__ Wv2, const float* __restrict__ Wo2,
                const float* __restrict__ g2,  const float* __restrict__ be2,
                const float* __restrict__ Wv3, const float* __restrict__ Wo3,
                const float* __restrict__ g3,  const float* __restrict__ be3,
                const float* __restrict__ Wf1, const float* __restrict__ bf1,
                const float* __restrict__ Wf2, const float* __restrict__ bf2,
                float* __restrict__ out)
{
    extern __shared__ float sm[];
    float* sX   = sm + OFF_X;
    float* sW1  = sm + OFF_W1;
    float* sW2  = sm + OFF_W2;
    int*   sEdge= (int*)(sm + OFF_E);
    float* sSf  = sm + OFF_SF;
    float* sX3  = sm + OFF_X3;
    float* sT   = sm + OVL_T;
    float* sT2  = sm + OVL_T2;
    float* sPart= sm + OVL_PART;
    float* sVp2 = sm + OVL_VP2;
    float* sVp3 = sm + OVL_VP3;
    float* sVv  = sm + OVL_VV;
    float* sHg2 = sm + OVL_HG2;
    float* sO10 = sm + OVL_O10;

    const int g    = blockIdx.x;
    const int tid  = threadIdx.x;
    const int warp = tid >> 5;
    const int lane = tid & 31;

    // ---------------- Phase 1: stage inputs ----------------
    for (int i = tid; i < NPG * DEG; i += 512)
        sEdge[i] = edge_src[g * (NPG * DEG) + i] - g * NPG;
    {
        const u64* fsrc = (const u64*)(feat + (size_t)g * NPG * DIN);
        for (int i = tid; i < (NPG * DIN) / 2; i += 512)
            *(u64*)&sX[2 * i] = fsrc[i];              // pitch 100 == DIN
    }
    for (int idx = tid; idx < H1D * (DIN / 2); idx += 512) {
        int o = idx / 50, kp = idx - o * 50;
        *(u64*)&sW1[o * PA + 2 * kp] = *(const u64*)&W1[o * DIN + 2 * kp];
    }
    for (int idx = tid; idx < DG * (H1D / 2); idx += 512) {
        int o = idx / 50, kp = idx - o * 50;
        *(u64*)&sW2[o * PA + 2 * kp] = *(const u64*)&W2[o * H1D + 2 * kp];
    }
    for (int i = tid; i < P2D; i += 512) sSf[i] = self_feat[g * P2D + i];
    for (int i = tid; i < P3D; i += 512) sX3[i] = x3d[g * P3D + i];
    __syncthreads();

    // ---------------- agg1 in REGISTERS -------------------------------------
    // Lane l holds k-chunks (pairs of dims) c = l and c = l+32 (l<18) of the
    // warp's 7 rows. All loads are full-warp contiguous -> conflict-free.
    u64 ac[7][2];
    #pragma unroll
    for (int i = 0; i < 7; ++i) { ac[i][0] = 0ull; ac[i][1] = 0ull; }
    {
        const bool has2 = (lane < 18);
        const int c0 = 2 * lane, c1 = 2 * lane + 64;
        #pragma unroll
        for (int i = 0; i < 7; ++i) {
            int n = warp + 16 * i;
            if (n < NPG) {
                int base = n * DEG;
                #pragma unroll
                for (int j = 0; j < DEG; ++j) {
                    int s = sEdge[base + j];
                    fadd2(ac[i][0], *(const u64*)&sX[s * DIN + c0]);
                    if (has2) fadd2(ac[i][1], *(const u64*)&sX[s * DIN + c1]);
                }
                const u64 inv2 = 0x3D8000003D800000ull;   // (1/16, 1/16)
                fmul2(ac[i][0], inv2);
                fmul2(ac[i][1], inv2);
            }
        }
    }

    // ---------------- GEMM1: h1 = relu(A @ W1^T + b1), regs only ------------
    int wr[4];
    #pragma unroll
    for (int j = 0; j < 4; ++j) {
        int c = lane + 32 * j;
        wr[j] = (c < H1D) ? c : 0;
    }
    float h[7][4];
    {
        u64 acc[7][4];
        #pragma unroll
        for (int i = 0; i < 7; ++i)
            #pragma unroll
            for (int j = 0; j < 4; ++j) acc[i][j] = 0ull;

        #pragma unroll 4
        for (int kp = 0; kp < 32; ++kp) {
            u64 w2[4];
            #pragma unroll
            for (int j = 0; j < 4; ++j)
                w2[j] = *(const u64*)&sW1[wr[j] * PA + 2 * kp];
            #pragma unroll
            for (int i = 0; i < 7; ++i) {
                u64 a = shfl64(ac[i][0], kp);
                #pragma unroll
                for (int j = 0; j < 4; ++j) ffma2(acc[i][j], a, w2[j]);
            }
        }
        #pragma unroll 3
        for (int kp = 32; kp < 50; ++kp) {
            u64 w2[4];
            #pragma unroll
            for (int j = 0; j < 4; ++j)
                w2[j] = *(const u64*)&sW1[wr[j] * PA + 2 * kp];
            #pragma unroll
            for (int i = 0; i < 7; ++i) {
                u64 a = shfl64(ac[i][1], kp - 32);
                #pragma unroll
                for (int j = 0; j < 4; ++j) ffma2(acc[i][j], a, w2[j]);
            }
        }
        float bb[4];
        #pragma unroll
        for (int j = 0; j < 4; ++j) {
            int c = lane + 32 * j;
            bb[j] = (c < H1D) ? b1[c] : 0.f;
        }
        #pragma unroll
        for (int i = 0; i < 7; ++i)
            #pragma unroll
            for (int j = 0; j < 4; ++j)
                h[i][j] = fmaxf(hsum2(acc[i][j]) + bb[j], 0.f);
    }

    // ---------------- repack h1 (col-per-lane) -> k-chunk-per-lane ----------
    // chunk c holds cols (2c, 2c+1); lane l keeps chunks l and l+32.
    u64 hc[7][2];
    {
        const int sl = (2 * lane) & 31;
        const int sh = (2 * lane + 1) & 31;
        const bool lo16 = (lane < 16);
        #pragma unroll
        for (int i = 0; i < 7; ++i) {
            float l0 = __shfl_sync(0xffffffffu, h[i][0], sl);
            float l1 = __shfl_sync(0xffffffffu, h[i][1], sl);
            float h0 = __shfl_sync(0xffffffffu, h[i][0], sh);
            float h1v = __shfl_sync(0xffffffffu, h[i][1], sh);
            hc[i][0] = pack2(lo16 ? l0 : l1, lo16 ? h0 : h1v);
            float l2 = __shfl_sync(0xffffffffu, h[i][2], sl);
            float l3 = __shfl_sync(0xffffffffu, h[i][3], sl);
            float h2 = __shfl_sync(0xffffffffu, h[i][2], sh);
            float h3 = __shfl_sync(0xffffffffu, h[i][3], sh);
            hc[i][1] = pack2(lo16 ? l2 : l3, lo16 ? h2 : h3);
        }
    }
    __syncthreads();   // all warps past agg1 feat reads -> sX reusable as sT

    // ---------------- GEMM2: t = h1 @ W2^T (pre-bias) -----------------------
    {
        const int w2r = (lane < DG) ? lane : 0;
        u64 acc2[7];
        #pragma unroll
        for (int i = 0; i < 7; ++i) acc2[i] = 0ull;

        #pragma unroll 4
        for (int kp = 0; kp < 32; ++kp) {
            u64 w = *(const u64*)&sW2[w2r * PA + 2 * kp];
            #pragma unroll
            for (int i = 0; i < 7; ++i)
                ffma2(acc2[i], shfl64(hc[i][0], kp), w);
        }
        #pragma unroll 3
        for (int kp = 32; kp < 50; ++kp) {
            u64 w = *(const u64*)&sW2[w2r * PA + 2 * kp];
            #pragma unroll
            for (int i = 0; i < 7; ++i)
                ffma2(acc2[i], shfl64(hc[i][1], kp - 32), w);
        }
        if (lane < DG) {
            #pragma unroll
            for (int i = 0; i < 7; ++i) {
                int r = warp + 16 * i;
                if (r < NPG) sT[r * PT + lane] = hsum2(acc2[i]);
            }
        }
    }
    __syncthreads();   // full t needed for aggregation 2

    // ---------------- agg2: mean over neighbors (20 dims) -------------------
    for (int n = warp; n < NPG; n += 16) {
        if (lane < DG) {
            float acc = 0.f;
            int base = n * DEG;
            #pragma unroll
            for (int j = 0; j < DEG; ++j)
                acc += sT[sEdge[base + j] * PT + lane];
            sT2[n * PT + lane] = acc * (1.f / DEG);
        }
    }
    __syncwarp();

    // ---------------- hg partials + attention V partials --------------------
    if (lane < DG) {
        float b = b2[lane];
        float acc = 0.f;
        for (int n = warp; n < NPG; n += 16)
            acc += fmaxf(sT2[n * PT + lane] + b, 0.f);
        sPart[warp * DG + lane] = acc;
    }
    {
        int j  = lane;
        int pg = warp;
        {   // v2: 200 dims in 16 chunks of 13 (clamped)
            int p0 = pg * 13, p1 = min(p0 + 13, P2D);
            float acc = 0.f;
            for (int p = p0; p < p1; ++p) acc = fmaf(Wv2[j * P2D + p], sSf[p], acc);
            sVp2[pg * 32 + j] = acc;
        }
        {   // v3: 100 dims in 16 chunks of 7 (clamped)
            int p0 = pg * 7, p1 = min(p0 + 7, P3D);
            float acc = 0.f;
            for (int p = p0; p < p1; ++p) acc = fmaf(Wv3[j * P3D + p], sX3[p], acc);
            sVp3[pg * 32 + j] = acc;
        }
    }
    __syncthreads();

    // ---------------- head (warp 0) -----------------------------------------
    if (tid < 32) {
        float v2 = 0.f, v3 = 0.f;
        #pragma unroll
        for (int pg = 0; pg < 16; ++pg) {
            v2 += sVp2[pg * 32 + lane];
            v3 += sVp3[pg * 32 + lane];
        }
        sVv[lane]      = v2;
        sVv[32 + lane] = v3;
        __syncwarp();

        float hg = 0.f, z2 = 0.f;
        if (lane < DG) {
            #pragma unroll
            for (int w = 0; w < 16; ++w) hg += sPart[w * DG + lane];
            hg *= (1.f / NPG);
            #pragma unroll
            for (int j = 0; j < 32; ++j) z2 = fmaf(Wo2[lane * 32 + j], sVv[j], z2);
        }
        float y = hg + z2;
        float t = (lane < DG) ? y : 0.f;
        #pragma unroll
        for (int o = 16; o > 0; o >>= 1) t += __shfl_xor_sync(0xffffffffu, t, o);
        float mu = t * (1.f / DG);
        float dv = (lane < DG) ? (y - mu) : 0.f;
        float t2 = dv * dv;
        #pragma unroll
        for (int o = 16; o > 0; o >>= 1) t2 += __shfl_xor_sync(0xffffffffu, t2, o);
        float inv = rsqrtf(t2 * (1.f / DG) + 1e-5f);
        float hg1 = (lane < DG) ? fmaf((y - mu) * inv, g2[lane], be2[lane]) : 0.f;

        float z3 = 0.f;
        if (lane < DG) {
            #pragma unroll
            for (int j = 0; j < 32; ++j) z3 = fmaf(Wo3[lane * 32 + j], sVv[32 + j], z3);
        }
        float y2 = hg1 + z3;
        t = (lane < DG) ? y2 : 0.f;
        #pragma unroll
        for (int o = 16; o > 0; o >>= 1) t += __shfl_xor_sync(0xffffffffu, t, o);
        mu = t * (1.f / DG);
        dv = (lane < DG) ? (y2 - mu) : 0.f;
        t2 = dv * dv;
        #pragma unroll
        for (int o = 16; o > 0; o >>= 1) t2 += __shfl_xor_sync(0xffffffffu, t2, o);
        inv = rsqrtf(t2 * (1.f / DG) + 1e-5f);
        if (lane < DG) sHg2[lane] = fmaf((y2 - mu) * inv, g3[lane], be3[lane]);
        __syncwarp();

        if (lane < 10) {
            float a = bf1[lane];
            #pragma unroll
            for (int d = 0; d < DG; ++d) a = fmaf(Wf1[lane * DG + d], sHg2[d], a);
            sO10[lane] = fmaxf(a, 0.f);
        }
        __syncwarp();

        if (lane == 0) {
            float o = bf2[0];
            #pragma unroll
            for (int i = 0; i < 10; ++i) o = fmaf(Wf2[i], sO10[i], o);
            out[g] = o;
        }
    }
}

extern "C" void kernel_launch(void* const* d_in, const int* in_sizes, int n_in,
                              void* d_out, int out_size) {
    const float* feat     = (const float*)d_in[0];
    const int*   edge_src = (const int*)  d_in[1];
    // d_in[2] = edge_dst (implicit: repeat(arange))
    const float* self_f   = (const float*)d_in[3];
    const float* x3d      = (const float*)d_in[4];
    const float* W1  = (const float*)d_in[5];
    const float* b1  = (const float*)d_in[6];
    const float* W2  = (const float*)d_in[7];
    const float* b2  = (const float*)d_in[8];
    // 9 Wq2, 10 Wk2 unused (softmax over length-1 token == 1)
    const float* Wv2 = (const float*)d_in[11];
    const float* Wo2 = (const float*)d_in[12];
    const float* g2  = (const float*)d_in[13];
    const float* be2 = (const float*)d_in[14];
    // 15 Wq3, 16 Wk3 unused
    const float* Wv3 = (const float*)d_in[17];
    const float* Wo3 = (const float*)d_in[18];
    const float* g3  = (const float*)d_in[19];
    const float* be3 = (const float*)d_in[20];
    const float* Wf1 = (const float*)d_in[21];
    const float* bf1 = (const float*)d_in[22];
    const float* Wf2 = (const float*)d_in[23];
    const float* bf2 = (const float*)d_in[24];
    float* out = (float*)d_out;

    cudaFuncSetAttribute(net_kernel, cudaFuncAttributeMaxDynamicSharedMemorySize,
                         SMEM_BYTES);
    net_kernel<<<512, 512, SMEM_BYTES>>>(feat, edge_src, self_f, x3d,
                                         W1, b1, W2, b2,
                                         Wv2, Wo2, g2, be2,
                                         Wv3, Wo3, g3, be3,
                                         Wf1, bf1, Wf2, bf2, out);
}

// round 13
// speedup vs baseline: 1.2987x; 1.2987x over previous
#include <cuda_runtime.h>
#include <cuda_fp16.h>
#include <cstdint>

// Fused batched GCN, one CTA per graph (512 x 100 nodes, deg 16).
// 384 threads/CTA, __launch_bounds__(384,2) -> TWO CTAs per SM (24 warps)
// for latency coverage. smem squeezed to ~109KB: W1/W2 in fp16 (expanded on
// load), edges packed u8, h1 overlays feat, t overlays A row-for-row,
// agg2+graph-mean fused into registers. GEMMs: packed fma.rn.f32x2 over k.
// Heads: softmax over a length-1 token == 1 -> Z=(x@Wv^T)@Wo^T; Wq/Wk dead.

#define NPG 100
#define DEG 16
#define DIN 100
#define H1D 100
#define DG  20
#define P2D 200
#define P3D 100
#define PWH 51      // u32 pitch of fp16 weight tiles (51 mod 32 = 19, CF)

// ---- shared memory layout (4-byte element offsets) ----
#define OFF_X    0                   // 10000  feat (pitch 100); h1 after GEMM1
#define OFF_W1   10000               // 5100 u32  W1 fp16 pairs (100 x 51)
#define OFF_A    15100               // 10000  agg1 (pitch 100); t overlays rows
#define OFF_W2   25100               // 1020 u32  W2 fp16 pairs (20 x 51)
#define OFF_E8   26120               // 400 u32   edges as u8 (16 per row)
#define OFF_SF   26520               // 200
#define OFF_X3   26720               // 104
#define OFF_PART 26824               // 12*20 = 240
#define OFF_VP2  27064               // 384
#define OFF_VP3  27448               // 384
#define OFF_VV   27832               // 64
#define OFF_HG2  27896               // 24
#define OFF_O10  27920               // 16
#define SMEM_ELEMS 27936
#define SMEM_BYTES (SMEM_ELEMS * 4)  // 111744 B =~ 109.1 KB -> 2 CTAs/SM

typedef unsigned long long u64;
typedef unsigned int u32;

static __device__ __forceinline__ void ffma2(u64& d, u64 a, u64 b) {
    asm("fma.rn.f32x2 %0, %1, %2, %0;" : "+l"(d) : "l"(a), "l"(b));
}
static __device__ __forceinline__ void fadd2(u64& d, u64 a) {
    asm("add.rn.f32x2 %0, %0, %1;" : "+l"(d) : "l"(a));
}
static __device__ __forceinline__ void fmul2(u64& d, u64 a) {
    asm("mul.rn.f32x2 %0, %0, %1;" : "+l"(d) : "l"(a));
}
static __device__ __forceinline__ void lds_v2u64(u64& a, u64& b, const float* p) {
    asm("ld.shared.v2.u64 {%0,%1}, [%2];"
        : "=l"(a), "=l"(b) : "l"(__cvta_generic_to_shared(p)));
}
static __device__ __forceinline__ float hsum2(u64 v) {
    float lo = __uint_as_float((u32)(v & 0xffffffffu));
    float hi = __uint_as_float((u32)(v >> 32));
    return lo + hi;
}
static __device__ __forceinline__ u64 pack2(float lo, float hi) {
    return (u64)__float_as_uint(lo) | ((u64)__float_as_uint(hi) << 32);
}
// fp16 pair (lo=k even, hi=k odd) -> packed f32x2
static __device__ __forceinline__ u64 h2w(u32 v) {
    __half2 h = *reinterpret_cast<__half2*>(&v);
    float2 f = __half22float2(h);
    return pack2(f.x, f.y);
}

__global__ __launch_bounds__(384, 2)
void net_kernel(const float* __restrict__ feat,
                const int*   __restrict__ edge_src,
                const float* __restrict__ self_feat,
                const float* __restrict__ x3d,
                const float* __restrict__ W1,  const float* __restrict__ b1,
                const float* __restrict__ W2,  const float* __restrict__ b2,
                const float* __restrict__ Wv2, const float* __restrict__ Wo2,
                const float* __restrict__ g2,  const float* __restrict__ be2,
                const float* __restrict__ Wv3, const float* __restrict__ Wo3,
                const float* __restrict__ g3,  const float* __restrict__ be3,
                const float* __restrict__ Wf1, const float* __restrict__ bf1,
                const float* __restrict__ Wf2, const float* __restrict__ bf2,
                float* __restrict__ out)
{
    extern __shared__ float sm[];
    float* sX   = sm + OFF_X;      // feat, then h1
    u32*   sW1u = (u32*)(sm + OFF_W1);
    float* sA   = sm + OFF_A;      // agg1, then t (cols 0..19 of each row)
    u32*   sW2u = (u32*)(sm + OFF_W2);
    u32*   sE8  = (u32*)(sm + OFF_E8);
    float* sSf  = sm + OFF_SF;
    float* sX3  = sm + OFF_X3;
    float* sPart= sm + OFF_PART;
    float* sVp2 = sm + OFF_VP2;
    float* sVp3 = sm + OFF_VP3;
    float* sVv  = sm + OFF_VV;
    float* sHg2 = sm + OFF_HG2;
    float* sO10 = sm + OFF_O10;

    const int g    = blockIdx.x;
    const int tid  = threadIdx.x;
    const int warp = tid >> 5;
    const int lane = tid & 31;
    const int NR   = (warp < 4) ? 9 : 8;   // rows warp + 12*i

    // ---------------- Phase 1: stage inputs ----------------
    {   // edges -> u8 packed, 4 per u32
        const int4* ePtr = (const int4*)(edge_src + (size_t)g * NPG * DEG);
        for (int q = tid; q < 400; q += 384) {
            int4 e = ePtr[q];
            int b = g * NPG;
            sE8[q] = (u32)(e.x - b) | ((u32)(e.y - b) << 8) |
                     ((u32)(e.z - b) << 16) | ((u32)(e.w - b) << 24);
        }
    }
    {   // feat 100x100 fp32
        const u64* fsrc = (const u64*)(feat + (size_t)g * NPG * DIN);
        for (int i = tid; i < (NPG * DIN) / 2; i += 384)
            *(u64*)&sX[2 * i] = fsrc[i];
    }
    // W1 -> fp16 pairs (even k in low half)
    for (int idx = tid; idx < H1D * 50; idx += 384) {
        int o = idx / 50, kp = idx - o * 50;
        float2 w = *(const float2*)&W1[o * DIN + 2 * kp];
        __half2 hv = __floats2half2_rn(w.x, w.y);
        sW1u[o * PWH + kp] = *reinterpret_cast<u32*>(&hv);
    }
    // W2 -> fp16 pairs
    for (int idx = tid; idx < DG * 50; idx += 384) {
        int o = idx / 50, kp = idx - o * 50;
        float2 w = *(const float2*)&W2[o * H1D + 2 * kp];
        __half2 hv = __floats2half2_rn(w.x, w.y);
        sW2u[o * PWH + kp] = *reinterpret_cast<u32*>(&hv);
    }
    for (int i = tid; i < P2D; i += 384) sSf[i] = self_feat[g * P2D + i];
    for (int i = tid; i < P3D; i += 384) sX3[i] = x3d[g * P3D + i];
    __syncthreads();

    // ---------------- agg1: mean of 16 nbrs (own rows) ----------------------
    if (lane < 25) {
        #pragma unroll
        for (int i = 0; i < 9; ++i) {
            int n = warp + 12 * i;
            if (n < NPG) {
                u64 a0 = 0ull, a1 = 0ull;
                uint4 ep = ((const uint4*)sE8)[n];
                u32 ew[4] = {ep.x, ep.y, ep.z, ep.w};
                #pragma unroll
                for (int q = 0; q < 4; ++q) {
                    #pragma unroll
                    for (int b = 0; b < 4; ++b) {
                        int s = (ew[q] >> (8 * b)) & 0xff;
                        u64 v0, v1;
                        lds_v2u64(v0, v1, &sX[s * DIN + (lane << 2)]);
                        fadd2(a0, v0);
                        fadd2(a1, v1);
                    }
                }
                const u64 inv2 = 0x3D8000003D800000ull;   // (1/16, 1/16)
                fmul2(a0, inv2);
                fmul2(a1, inv2);
                *(u64*)&sA[n * 100 + (lane << 2)]     = a0;
                *(u64*)&sA[n * 100 + (lane << 2) + 2] = a1;
            }
        }
    }
    __syncwarp();

    // ---------------- GEMM1: h1 = relu(A @ W1^T + b1), 2 col passes ---------
    #pragma unroll 1
    for (int cp = 0; cp < 2; ++cp) {
        const int c0 = lane + 64 * cp;
        const int c1 = c0 + 32;
        const bool c1v = (c1 < H1D);
        const int c1r = c1v ? c1 : 0;

        u64 acc[9][2];
        #pragma unroll
        for (int i = 0; i < 9; ++i) { acc[i][0] = 0ull; acc[i][1] = 0ull; }

        #pragma unroll 2
        for (int p = 0; p < 25; ++p) {          // k pair-of-pairs: k = 4p..4p+3
            u64 w0a = h2w(sW1u[c0 * PWH + 2 * p]);
            u64 w0b = h2w(sW1u[c0 * PWH + 2 * p + 1]);
            u64 w1a = h2w(sW1u[c1r * PWH + 2 * p]);
            u64 w1b = h2w(sW1u[c1r * PWH + 2 * p + 1]);
            #pragma unroll
            for (int i = 0; i < 9; ++i) {
                int rc = warp + 12 * i; rc = (rc < NPG) ? rc : (NPG - 1);
                u64 vlo, vhi;
                lds_v2u64(vlo, vhi, &sA[rc * 100 + 4 * p]);   // warp-uniform bc
                ffma2(acc[i][0], vlo, w0a);
                ffma2(acc[i][1], vlo, w1a);
                ffma2(acc[i][0], vhi, w0b);
                ffma2(acc[i][1], vhi, w1b);
            }
        }
        if (cp == 0) __syncthreads();   // all agg1 sX reads done before h1 writes

        float bb0 = b1[c0];
        float bb1 = c1v ? b1[c1] : 0.f;
        #pragma unroll
        for (int i = 0; i < 9; ++i) {
            int r = warp + 12 * i;
            if (r < NPG) {
                sX[r * 100 + c0] = fmaxf(hsum2(acc[i][0]) + bb0, 0.f);
                if (c1v) sX[r * 100 + c1] = fmaxf(hsum2(acc[i][1]) + bb1, 0.f);
            }
        }
    }
    __syncwarp();

    // ---------------- GEMM2: t = h1 @ W2^T (pre-bias) -> sA rows ------------
    {
        const int c = (lane < DG) ? lane : 0;
        u64 acc2[9];
        #pragma unroll
        for (int i = 0; i < 9; ++i) acc2[i] = 0ull;

        #pragma unroll 2
        for (int p = 0; p < 25; ++p) {
            u64 wa = h2w(sW2u[c * PWH + 2 * p]);
            u64 wb = h2w(sW2u[c * PWH + 2 * p + 1]);
            #pragma unroll
            for (int i = 0; i < 9; ++i) {
                int rc = warp + 12 * i; rc = (rc < NPG) ? rc : (NPG - 1);
                u64 vlo, vhi;
                lds_v2u64(vlo, vhi, &sX[rc * 100 + 4 * p]);   // h1 bc (own rows)
                ffma2(acc2[i], vlo, wa);
                ffma2(acc2[i], vhi, wb);
            }
        }
        if (lane < DG) {
            #pragma unroll
            for (int i = 0; i < 9; ++i) {
                int r = warp + 12 * i;
                if (r < NPG) sA[r * 100 + lane] = hsum2(acc2[i]);  // t overlay
            }
        }
    }
    __syncthreads();   // full t needed for aggregation 2

    // ---------------- agg2 + b2 + relu + graph-mean partial (fused) ---------
    {
        float b2l = (lane < DG) ? b2[lane] : 0.f;
        float hacc = 0.f;
        #pragma unroll
        for (int i = 0; i < 9; ++i) {
            int n = warp + 12 * i;
            if (n < NPG) {
                uint4 ep = ((const uint4*)sE8)[n];
                u32 ew[4] = {ep.x, ep.y, ep.z, ep.w};
                float t2 = 0.f;
                #pragma unroll
                for (int q = 0; q < 4; ++q) {
                    #pragma unroll
                    for (int b = 0; b < 4; ++b) {
                        int s = (ew[q] >> (8 * b)) & 0xff;
                        t2 += sA[s * 100 + ((lane < DG) ? lane : 0)];
                    }
                }
                hacc += fmaxf(t2 * (1.f / DEG) + b2l, 0.f);
            }
        }
        if (lane < DG) sPart[warp * DG + lane] = hacc;
    }
    {   // attention V partials: 12 chunks
        int j  = lane;
        int pg = warp;
        {   // v2: 200 dims in 12 chunks of 17
            int p0 = pg * 17, p1 = min(p0 + 17, P2D);
            float acc = 0.f;
            for (int p = p0; p < p1; ++p) acc = fmaf(Wv2[j * P2D + p], sSf[p], acc);
            sVp2[pg * 32 + j] = acc;
        }
        {   // v3: 100 dims in 12 chunks of 9
            int p0 = pg * 9, p1 = min(p0 + 9, P3D);
            float acc = 0.f;
            for (int p = p0; p < p1; ++p) acc = fmaf(Wv3[j * P3D + p], sX3[p], acc);
            sVp3[pg * 32 + j] = acc;
        }
    }
    __syncthreads();

    // ---------------- head (warp 0) -----------------------------------------
    if (tid < 32) {
        float v2 = 0.f, v3 = 0.f;
        #pragma unroll
        for (int pg = 0; pg < 12; ++pg) {
            v2 += sVp2[pg * 32 + lane];
            v3 += sVp3[pg * 32 + lane];
        }
        sVv[lane]      = v2;
        sVv[32 + lane] = v3;
        __syncwarp();

        float hg = 0.f, z2 = 0.f;
        if (lane < DG) {
            #pragma unroll
            for (int w = 0; w < 12; ++w) hg += sPart[w * DG + lane];
            hg *= (1.f / NPG);
            #pragma unroll
            for (int j = 0; j < 32; ++j) z2 = fmaf(Wo2[lane * 32 + j], sVv[j], z2);
        }
        float y = hg + z2;
        float t = (lane < DG) ? y : 0.f;
        #pragma unroll
        for (int o = 16; o > 0; o >>= 1) t += __shfl_xor_sync(0xffffffffu, t, o);
        float mu = t * (1.f / DG);
        float dv = (lane < DG) ? (y - mu) : 0.f;
        float t2 = dv * dv;
        #pragma unroll
        for (int o = 16; o > 0; o >>= 1) t2 += __shfl_xor_sync(0xffffffffu, t2, o);
        float inv = rsqrtf(t2 * (1.f / DG) + 1e-5f);
        float hg1 = (lane < DG) ? fmaf((y - mu) * inv, g2[lane], be2[lane]) : 0.f;

        float z3 = 0.f;
        if (lane < DG) {
            #pragma unroll
            for (int j = 0; j < 32; ++j) z3 = fmaf(Wo3[lane * 32 + j], sVv[32 + j], z3);
        }
        float y2 = hg1 + z3;
        t = (lane < DG) ? y2 : 0.f;
        #pragma unroll
        for (int o = 16; o > 0; o >>= 1) t += __shfl_xor_sync(0xffffffffu, t, o);
        mu = t * (1.f / DG);
        dv = (lane < DG) ? (y2 - mu) : 0.f;
        t2 = dv * dv;
        #pragma unroll
        for (int o = 16; o > 0; o >>= 1) t2 += __shfl_xor_sync(0xffffffffu, t2, o);
        inv = rsqrtf(t2 * (1.f / DG) + 1e-5f);
        if (lane < DG) sHg2[lane] = fmaf((y2 - mu) * inv, g3[lane], be3[lane]);
        __syncwarp();

        if (lane < 10) {
            float a = bf1[lane];
            #pragma unroll
            for (int d = 0; d < DG; ++d) a = fmaf(Wf1[lane * DG + d], sHg2[d], a);
            sO10[lane] = fmaxf(a, 0.f);
        }
        __syncwarp();

        if (lane == 0) {
            float o = bf2[0];
            #pragma unroll
            for (int i = 0; i < 10; ++i) o = fmaf(Wf2[i], sO10[i], o);
            out[g] = o;
        }
    }
}

extern "C" void kernel_launch(void* const* d_in, const int* in_sizes, int n_in,
                              void* d_out, int out_size) {
    const float* feat     = (const float*)d_in[0];
    const int*   edge_src = (const int*)  d_in[1];
    // d_in[2] = edge_dst (implicit: repeat(arange))
    const float* self_f   = (const float*)d_in[3];
    const float* x3d      = (const float*)d_in[4];
    const float* W1  = (const float*)d_in[5];
    const float* b1  = (const float*)d_in[6];
    const float* W2  = (const float*)d_in[7];
    const float* b2  = (const float*)d_in[8];
    // 9 Wq2, 10 Wk2 unused (softmax over length-1 token == 1)
    const float* Wv2 = (const float*)d_in[11];
    const float* Wo2 = (const float*)d_in[12];
    const float* g2  = (const float*)d_in[13];
    const float* be2 = (const float*)d_in[14];
    // 15 Wq3, 16 Wk3 unused
    const float* Wv3 = (const float*)d_in[17];
    const float* Wo3 = (const float*)d_in[18];
    const float* g3  = (const float*)d_in[19];
    const float* be3 = (const float*)d_in[20];
    const float* Wf1 = (const float*)d_in[21];
    const float* bf1 = (const float*)d_in[22];
    const float* Wf2 = (const float*)d_in[23];
    const float* bf2 = (const float*)d_in[24];
    float* out = (float*)d_out;

    cudaFuncSetAttribute(net_kernel, cudaFuncAttributeMaxDynamicSharedMemorySize,
                         SMEM_BYTES);
    net_kernel<<<512, 384, SMEM_BYTES>>>(feat, edge_src, self_f, x3d,
                                         W1, b1, W2, b2,
                                         Wv2, Wo2, g2, be2,
                                         Wv3, Wo3, g3, be3,
                                         Wf1, bf1, Wf2, bf2, out);
}

// round 15
// speedup vs baseline: 1.4207x; 1.0940x over previous
#include <cuda_runtime.h>
#include <cuda_fp16.h>
#include <cstdint>

// Fused batched GCN, one CTA per graph (512 x 100 nodes, deg 16).
// 384 thr/CTA, 2 CTAs/SM. Crossbar diet: feat fp16 (agg1 via HADD2 groups),
// W1 fp16 u64 loads, W2 fp32, h1 overlays A row-for-row (owner-warp private),
// t overlays h1. GEMMs: packed fma.rn.f32x2 over k. Heads: softmax over a
// length-1 token == 1 -> Z=(x@Wv^T)@Wo^T; Wq/Wk dead.

#define NPG 100
#define DEG 16
#define DIN 100
#define H1D 100
#define DG  20
#define P2D 200
#define P3D 100
#define PW1 27     // u64 pitch of fp16 W1 (odd -> conflict-free LDS.64)
#define PW2 102    // float pitch of fp32 W2 (u64 stride 51, odd -> CF)

// ---- shared memory layout (4-byte element offsets) ----
#define OFF_XH   0          // 5000  feat fp16 (10000 halves, pitch 100 halves)
#define OFF_A    5000       // 10000 A (pitch 100); h1 then t overlay rows
#define OFF_W1   15000      // 5400  W1 fp16 (100 x 27 u64)
#define OFF_W2   20400      // 2040  W2 fp32 (20 x 102)
#define OFF_E8   22440      // 400   edges u8 packed
#define OFF_SF   22840      // 200
#define OFF_X3   23040      // 104
#define OFF_PART 23144      // 240
#define OFF_VP2  23384      // 384
#define OFF_VP3  23768      // 384
#define OFF_VV   24152      // 64
#define OFF_HG2  24216      // 24
#define OFF_O10  24240      // 16
#define SMEM_ELEMS 24256
#define SMEM_BYTES (SMEM_ELEMS * 4)   // 97024 B -> 2 CTAs/SM

typedef unsigned long long u64;
typedef unsigned int u32;

static __device__ __forceinline__ void ffma2(u64& d, u64 a, u64 b) {
    asm("fma.rn.f32x2 %0, %1, %2, %0;" : "+l"(d) : "l"(a), "l"(b));
}
static __device__ __forceinline__ void lds_v2u64(u64& a, u64& b, const float* p) {
    asm("ld.shared.v2.u64 {%0,%1}, [%2];"
        : "=l"(a), "=l"(b) : "l"(__cvta_generic_to_shared(p)));
}
static __device__ __forceinline__ void lds_v2u32(u32& a, u32& b, const void* p) {
    asm("ld.shared.v2.u32 {%0,%1}, [%2];"
        : "=r"(a), "=r"(b) : "l"(__cvta_generic_to_shared(p)));
}
static __device__ __forceinline__ float hsum2(u64 v) {
    float lo = __uint_as_float((u32)(v & 0xffffffffu));
    float hi = __uint_as_float((u32)(v >> 32));
    return lo + hi;
}
static __device__ __forceinline__ u64 pack2(float lo, float hi) {
    return (u64)__float_as_uint(lo) | ((u64)__float_as_uint(hi) << 32);
}
static __device__ __forceinline__ u64 h2w(u32 v) {   // fp16 pair -> f32x2
    __half2 h = *reinterpret_cast<__half2*>(&v);
    float2 f = __half22float2(h);
    return pack2(f.x, f.y);
}
static __device__ __forceinline__ __half2 asH2(u32 v) {
    return *reinterpret_cast<__half2*>(&v);
}

__global__ __launch_bounds__(384, 2)
void net_kernel(const float* __restrict__ feat,
                const int*   __restrict__ edge_src,
                const float* __restrict__ self_feat,
                const float* __restrict__ x3d,
                const float* __restrict__ W1,  const float* __restrict__ b1,
                const float* __restrict__ W2,  const float* __restrict__ b2,
                const float* __restrict__ Wv2, const float* __restrict__ Wo2,
                const float* __restrict__ g2,  const float* __restrict__ be2,
                const float* __restrict__ Wv3, const float* __restrict__ Wo3,
                const float* __restrict__ g3,  const float* __restrict__ be3,
                const float* __restrict__ Wf1, const float* __restrict__ bf1,
                const float* __restrict__ Wf2, const float* __restrict__ bf2,
                float* __restrict__ out)
{
    extern __shared__ float sm[];
    char*  sXh  = (char*)(sm + OFF_XH);      // fp16 feat, pitch 200 bytes/row
    float* sA   = sm + OFF_A;                // A -> h1 -> t (per-row overlay)
    u64*   sW1u = (u64*)(sm + OFF_W1);
    float* sW2f = sm + OFF_W2;
    u32*   sE8  = (u32*)(sm + OFF_E8);
    float* sSf  = sm + OFF_SF;
    float* sX3  = sm + OFF_X3;
    float* sPart= sm + OFF_PART;
    float* sVp2 = sm + OFF_VP2;
    float* sVp3 = sm + OFF_VP3;
    float* sVv  = sm + OFF_VV;
    float* sHg2 = sm + OFF_HG2;
    float* sO10 = sm + OFF_O10;

    const int g    = blockIdx.x;
    const int tid  = threadIdx.x;
    const int warp = tid >> 5;
    const int lane = tid & 31;

    // ---------------- Phase 1: stage inputs ----------------
    {   // edges -> u8 packed, 4 per u32
        const int4* ePtr = (const int4*)(edge_src + (size_t)g * NPG * DEG);
        for (int q = tid; q < 400; q += 384) {
            int4 e = ePtr[q];
            int b = g * NPG;
            sE8[q] = (u32)(e.x - b) | ((u32)(e.y - b) << 8) |
                     ((u32)(e.z - b) << 16) | ((u32)(e.w - b) << 24);
        }
    }
    {   // feat fp32 -> fp16 (contiguous, pitch 100 halves == row-major)
        const float4* fsrc = (const float4*)(feat + (size_t)g * NPG * DIN);
        for (int i = tid; i < 2500; i += 384) {
            float4 f = fsrc[i];
            __half2 a = __floats2half2_rn(f.x, f.y);
            __half2 b = __floats2half2_rn(f.z, f.w);
            *(u64*)(sXh + i * 8) =
                (u64)(*reinterpret_cast<u32*>(&a)) |
                ((u64)(*reinterpret_cast<u32*>(&b)) << 32);
        }
    }
    // W1 -> fp16 quads (dims 4p..4p+3 in one u64)
    {
        const float4* wsrc = (const float4*)W1;
        for (int idx = tid; idx < 2500; idx += 384) {
            int o = idx / 25, p = idx - o * 25;
            float4 w = wsrc[o * 25 + p];
            __half2 a = __floats2half2_rn(w.x, w.y);
            __half2 b = __floats2half2_rn(w.z, w.w);
            sW1u[o * PW1 + p] =
                (u64)(*reinterpret_cast<u32*>(&a)) |
                ((u64)(*reinterpret_cast<u32*>(&b)) << 32);
        }
    }
    // W2 fp32 -> pitch 102
    for (int idx = tid; idx < DG * 50; idx += 384) {
        int o = idx / 50, kp = idx - o * 50;
        *(u64*)&sW2f[o * PW2 + 2 * kp] = *(const u64*)&W2[o * H1D + 2 * kp];
    }
    for (int i = tid; i < P2D; i += 384) sSf[i] = self_feat[g * P2D + i];
    for (int i = tid; i < P3D; i += 384) sX3[i] = x3d[g * P3D + i];
    __syncthreads();

    // ---------------- agg1: SUM of 16 nbrs (fp16 HADD2, 4 groups of 4) ------
    // /16 deferred to GEMM1 epilogue. Lane<25 handles dims 4*lane..4*lane+3.
    if (lane < 25) {
        #pragma unroll
        for (int i = 0; i < 9; ++i) {
            int n = warp + 12 * i;
            if (n < NPG) {
                uint4 ep = ((const uint4*)sE8)[n];
                u32 ew[4] = {ep.x, ep.y, ep.z, ep.w};
                __half2 g0[4], g1[4];
                #pragma unroll
                for (int q = 0; q < 4; ++q) {
                    g0[q] = __floats2half2_rn(0.f, 0.f);
                    g1[q] = g0[q];
                    #pragma unroll
                    for (int b = 0; b < 4; ++b) {
                        int s = (ew[q] >> (8 * b)) & 0xff;
                        u32 lo, hi;
                        lds_v2u32(lo, hi, sXh + s * 200 + lane * 8);
                        g0[q] = __hadd2(g0[q], asH2(lo));
                        g1[q] = __hadd2(g1[q], asH2(hi));
                    }
                }
                __half2 s0 = __hadd2(__hadd2(g0[0], g0[1]), __hadd2(g0[2], g0[3]));
                __half2 s1 = __hadd2(__hadd2(g1[0], g1[1]), __hadd2(g1[2], g1[3]));
                float2 f0 = __half22float2(s0);
                float2 f1 = __half22float2(s1);
                *(u64*)&sA[n * 100 + 4 * lane]     = pack2(f0.x, f0.y);
                *(u64*)&sA[n * 100 + 4 * lane + 2] = pack2(f1.x, f1.y);
            }
        }
    }
    __syncwarp();

    // ---------------- GEMM1: h1 = relu((A @ W1^T)/16 + b1) ------------------
    // 2 col passes; pass-0 results carried in regs, all h1 stores after pass 1
    // (h1 overlays sA -> must not clobber A before pass-1 reads it).
    float h0[9][2];
    {
        const float inv16 = 1.f / 16.f;
        #pragma unroll 1
        for (int cp = 0; cp < 2; ++cp) {
            const int c0 = lane + 64 * cp;
            const int c1 = c0 + 32;
            const bool c1v = (c1 < H1D);
            const int c1r = c1v ? c1 : 0;

            u64 acc[9][2];
            #pragma unroll
            for (int i = 0; i < 9; ++i) { acc[i][0] = 0ull; acc[i][1] = 0ull; }

            #pragma unroll 2
            for (int p = 0; p < 25; ++p) {       // dims 4p..4p+3
                u64 wq0 = sW1u[c0 * PW1 + p];
                u64 wq1 = sW1u[c1r * PW1 + p];
                u64 w0a = h2w((u32)wq0), w0b = h2w((u32)(wq0 >> 32));
                u64 w1a = h2w((u32)wq1), w1b = h2w((u32)(wq1 >> 32));
                #pragma unroll
                for (int i = 0; i < 9; ++i) {
                    int rc = warp + 12 * i; rc = (rc < NPG) ? rc : (NPG - 1);
                    u64 vlo, vhi;
                    lds_v2u64(vlo, vhi, &sA[rc * 100 + 4 * p]);  // warp-uniform
                    ffma2(acc[i][0], vlo, w0a);
                    ffma2(acc[i][1], vlo, w1a);
                    ffma2(acc[i][0], vhi, w0b);
                    ffma2(acc[i][1], vhi, w1b);
                }
            }
            float bb0 = b1[c0];
            float bb1 = c1v ? b1[c1] : 0.f;
            if (cp == 0) {
                #pragma unroll
                for (int i = 0; i < 9; ++i) {
                    h0[i][0] = fmaxf(fmaf(hsum2(acc[i][0]), inv16, bb0), 0.f);
                    h0[i][1] = fmaxf(fmaf(hsum2(acc[i][1]), inv16, bb1), 0.f);
                }
            } else {
                // all A reads done -> write h1 over sA (own rows only)
                #pragma unroll
                for (int i = 0; i < 9; ++i) {
                    int r = warp + 12 * i;
                    if (r < NPG) {
                        sA[r * 100 + lane]      = h0[i][0];
                        sA[r * 100 + lane + 32] = h0[i][1];
                        sA[r * 100 + c0] =
                            fmaxf(fmaf(hsum2(acc[i][0]), inv16, bb0), 0.f);
                        if (c1v)
                            sA[r * 100 + c1] =
                                fmaxf(fmaf(hsum2(acc[i][1]), inv16, bb1), 0.f);
                    }
                }
            }
        }
    }
    __syncwarp();

    // ---------------- GEMM2: t = h1 @ W2^T (pre-bias) -> sA cols 0..19 ------
    {
        const int c = (lane < DG) ? lane : 0;
        u64 acc2[9];
        #pragma unroll
        for (int i = 0; i < 9; ++i) acc2[i] = 0ull;

        #pragma unroll 2
        for (int p = 0; p < 25; ++p) {
            u64 wa = *(const u64*)&sW2f[c * PW2 + 4 * p];
            u64 wb = *(const u64*)&sW2f[c * PW2 + 4 * p + 2];
            #pragma unroll
            for (int i = 0; i < 9; ++i) {
                int rc = warp + 12 * i; rc = (rc < NPG) ? rc : (NPG - 1);
                u64 vlo, vhi;
                lds_v2u64(vlo, vhi, &sA[rc * 100 + 4 * p]);   // h1 bc (own rows)
                ffma2(acc2[i], vlo, wa);
                ffma2(acc2[i], vhi, wb);
            }
        }
        if (lane < DG) {
            #pragma unroll
            for (int i = 0; i < 9; ++i) {
                int r = warp + 12 * i;
                if (r < NPG) sA[r * 100 + lane] = hsum2(acc2[i]);  // t overlay
            }
        }
    }
    __syncthreads();   // full t needed for aggregation 2

    // ---------------- agg2 + b2 + relu + graph-mean partial (fused) ---------
    {
        float b2l = (lane < DG) ? b2[lane] : 0.f;
        int cl = (lane < DG) ? lane : 0;
        float hacc = 0.f;
        #pragma unroll
        for (int i = 0; i < 9; ++i) {
            int n = warp + 12 * i;
            if (n < NPG) {
                uint4 ep = ((const uint4*)sE8)[n];
                u32 ew[4] = {ep.x, ep.y, ep.z, ep.w};
                float t2 = 0.f;
                #pragma unroll
                for (int q = 0; q < 4; ++q) {
                    #pragma unroll
                    for (int b = 0; b < 4; ++b) {
                        int s = (ew[q] >> (8 * b)) & 0xff;
                        t2 += sA[s * 100 + cl];
                    }
                }
                hacc += fmaxf(t2 * (1.f / DEG) + b2l, 0.f);
            }
        }
        if (lane < DG) sPart[warp * DG + lane] = hacc;
    }
    {   // attention V partials: 12 chunks
        int j  = lane;
        int pg = warp;
        {   // v2: 200 dims in 12 chunks of 17
            int p0 = pg * 17, p1 = min(p0 + 17, P2D);
            float acc = 0.f;
            for (int p = p0; p < p1; ++p) acc = fmaf(Wv2[j * P2D + p], sSf[p], acc);
            sVp2[pg * 32 + j] = acc;
        }
        {   // v3: 100 dims in 12 chunks of 9
            int p0 = pg * 9, p1 = min(p0 + 9, P3D);
            float acc = 0.f;
            for (int p = p0; p < p1; ++p) acc = fmaf(Wv3[j * P3D + p], sX3[p], acc);
            sVp3[pg * 32 + j] = acc;
        }
    }
    __syncthreads();

    // ---------------- head (warp 0) -----------------------------------------
    if (tid < 32) {
        float v2 = 0.f, v3 = 0.f;
        #pragma unroll
        for (int pg = 0; pg < 12; ++pg) {
            v2 += sVp2[pg * 32 + lane];
            v3 += sVp3[pg * 32 + lane];
        }
        sVv[lane]      = v2;
        sVv[32 + lane] = v3;
        __syncwarp();

        float hg = 0.f, z2 = 0.f;
        if (lane < DG) {
            #pragma unroll
            for (int w = 0; w < 12; ++w) hg += sPart[w * DG + lane];
            hg *= (1.f / NPG);
            #pragma unroll
            for (int j = 0; j < 32; ++j) z2 = fmaf(Wo2[lane * 32 + j], sVv[j], z2);
        }
        float y = hg + z2;
        float t = (lane < DG) ? y : 0.f;
        #pragma unroll
        for (int o = 16; o > 0; o >>= 1) t += __shfl_xor_sync(0xffffffffu, t, o);
        float mu = t * (1.f / DG);
        float dv = (lane < DG) ? (y - mu) : 0.f;
        float t2 = dv * dv;
        #pragma unroll
        for (int o = 16; o > 0; o >>= 1) t2 += __shfl_xor_sync(0xffffffffu, t2, o);
        float inv = rsqrtf(t2 * (1.f / DG) + 1e-5f);
        float hg1 = (lane < DG) ? fmaf((y - mu) * inv, g2[lane], be2[lane]) : 0.f;

        float z3 = 0.f;
        if (lane < DG) {
            #pragma unroll
            for (int j = 0; j < 32; ++j) z3 = fmaf(Wo3[lane * 32 + j], sVv[32 + j], z3);
        }
        float y2 = hg1 + z3;
        t = (lane < DG) ? y2 : 0.f;
        #pragma unroll
        for (int o = 16; o > 0; o >>= 1) t += __shfl_xor_sync(0xffffffffu, t, o);
        mu = t * (1.f / DG);
        dv = (lane < DG) ? (y2 - mu) : 0.f;
        t2 = dv * dv;
        #pragma unroll
        for (int o = 16; o > 0; o >>= 1) t2 += __shfl_xor_sync(0xffffffffu, t2, o);
        inv = rsqrtf(t2 * (1.f / DG) + 1e-5f);
        if (lane < DG) sHg2[lane] = fmaf((y2 - mu) * inv, g3[lane], be3[lane]);
        __syncwarp();

        if (lane < 10) {
            float a = bf1[lane];
            #pragma unroll
            for (int d = 0; d < DG; ++d) a = fmaf(Wf1[lane * DG + d], sHg2[d], a);
            sO10[lane] = fmaxf(a, 0.f);
        }
        __syncwarp();

        if (lane == 0) {
            float o = bf2[0];
            #pragma unroll
            for (int i = 0; i < 10; ++i) o = fmaf(Wf2[i], sO10[i], o);
            out[g] = o;
        }
    }
}

extern "C" void kernel_launch(void* const* d_in, const int* in_sizes, int n_in,
                              void* d_out, int out_size) {
    const float* feat     = (const float*)d_in[0];
    const int*   edge_src = (const int*)  d_in[1];
    // d_in[2] = edge_dst (implicit: repeat(arange))
    const float* self_f   = (const float*)d_in[3];
    const float* x3d      = (const float*)d_in[4];
    const float* W1  = (const float*)d_in[5];
    const float* b1  = (const float*)d_in[6];
    const float* W2  = (const float*)d_in[7];
    const float* b2  = (const float*)d_in[8];
    // 9 Wq2, 10 Wk2 unused (softmax over length-1 token == 1)
    const float* Wv2 = (const float*)d_in[11];
    const float* Wo2 = (const float*)d_in[12];
    const float* g2  = (const float*)d_in[13];
    const float* be2 = (const float*)d_in[14];
    // 15 Wq3, 16 Wk3 unused
    const float* Wv3 = (const float*)d_in[17];
    const float* Wo3 = (const float*)d_in[18];
    const float* g3  = (const float*)d_in[19];
    const float* be3 = (const float*)d_in[20];
    const float* Wf1 = (const float*)d_in[21];
    const float* bf1 = (const float*)d_in[22];
    const float* Wf2 = (const float*)d_in[23];
    const float* bf2 = (const float*)d_in[24];
    float* out = (float*)d_out;

    cudaFuncSetAttribute(net_kernel, cudaFuncAttributeMaxDynamicSharedMemorySize,
                         SMEM_BYTES);
    net_kernel<<<512, 384, SMEM_BYTES>>>(feat, edge_src, self_f, x3d,
                                         W1, b1, W2, b2,
                                         Wv2, Wo2, g2, be2,
                                         Wv3, Wo3, g3, be3,
                                         Wf1, bf1, Wf2, bf2, out);
}